// round 16
// baseline (speedup 1.0000x reference)
#include <cuda_runtime.h>
#include <cuda_fp16.h>
#include <cstdint>

// L1Attn: out[b,i,j,h] = -(1/8) * sum_d |q[b,j,h,d] - k[b,i,h,d]|
// B=8, S=1024, H=8, D=64. Output [B,S,S,H] (i = keys, j = queries).
//
// Dual-pipe hybrid: d 0..31 in fp16 (HSUB2/HABS2/HADD2, fma pipe);
// d 32..63 in s16 fixed-point via vabsdiff2.add (SAD, alu pipe,
// 1 instr per 2 terms incl. accumulation, exact integer accum).
// Convert kernel quantizes once into 4 scratch arrays. Persistent block
// over NI=8 i-tiles, q resident, k double-buffered (R15 structure).
// Rows padded to 80 B (20 words) -> all LDS.128 conflict-free.

namespace {
constexpr int S  = 1024;
constexpr int H  = 8;
constexpr int D  = 64;
constexpr int DH = 32;     // d per path
constexpr int NT = 256;
constexpr int TI = 8;      // i per tile
constexpr int NI = 8;      // i-tiles per block
constexpr int JB = 64;     // j per block: 32 (w,jl) slots x 2 u
constexpr int NU = 2;      // j outputs per thread
constexpr int RW = 40;     // elems per row: 32 d + 8 pad (80 B = 20 words)
constexpr int QR = JB * H;             // 512 q rows
constexpr int KR = TI * H;             // 64 k rows
constexpr int Q_ELEM = QR * RW;        // 20480 per array
constexpr int K_ELEM = KR * RW;        // 2560  per array per buffer
// smem (bytes): qh + qi + 2*(kh + ki), all 2B elems
constexpr unsigned SMEM_BYTES = (Q_ELEM * 2 + 2 * (K_ELEM * 2)) * 2;  // 102400
constexpr int NROW = 8 * S * H;        // 65536 rows per tensor
constexpr float SC_I  = 4096.0f;
constexpr float SC_IR = 1.0f / 4096.0f;
static_assert(S % JB == 0 && S % (TI * NI) == 0, "tiling must divide S");

struct __align__(8)  H4 { __half2 a, b; };
struct __align__(16) H8 { __half2 a, b, c, d; };
struct __align__(16) U4 { uint32_t x, y, z, w; };
}  // namespace

__device__ __half qh_g[NROW * DH];
__device__ __half kh_g[NROW * DH];
__device__ short  qi_g[NROW * DH];
__device__ short  ki_g[NROW * DH];

__device__ __forceinline__ uint32_t pack_s16(float x, float y) {
    int ix = __float2int_rn(fminf(fmaxf(x * SC_I, -32767.f), 32767.f));
    int iy = __float2int_rn(fminf(fmaxf(y * SC_I, -32767.f), 32767.f));
    return (uint32_t)(unsigned short)ix | ((uint32_t)(unsigned short)iy << 16);
}

__global__ void convert_kernel(const float* __restrict__ q,
                               const float* __restrict__ k, int n4) {
    int idx = blockIdx.x * blockDim.x + threadIdx.x;
    if (idx >= n4) return;
    int row = idx >> 4;       // (b,s,h) row
    int g   = idx & 15;       // float4 group within 64 d
    float4 qv = reinterpret_cast<const float4*>(q)[idx];
    float4 kv = reinterpret_cast<const float4*>(k)[idx];
    if (g < 8) {              // fp16 path: d 0..31
        H4 qh, kh;
        qh.a = __floats2half2_rn(qv.x, qv.y);
        qh.b = __floats2half2_rn(qv.z, qv.w);
        kh.a = __floats2half2_rn(kv.x, kv.y);
        kh.b = __floats2half2_rn(kv.z, kv.w);
        *reinterpret_cast<H4*>(qh_g + row * DH + g * 4) = qh;
        *reinterpret_cast<H4*>(kh_g + row * DH + g * 4) = kh;
    } else {                  // int path: d 32..63
        int o = (g - 8) * 4;
        uint2 qi, ki;
        qi.x = pack_s16(qv.x, qv.y);
        qi.y = pack_s16(qv.z, qv.w);
        ki.x = pack_s16(kv.x, kv.y);
        ki.y = pack_s16(kv.z, kv.w);
        *reinterpret_cast<uint2*>(qi_g + row * DH + o) = qi;
        *reinterpret_cast<uint2*>(ki_g + row * DH + o) = ki;
    }
}

__device__ __forceinline__ int sad2(int acc, uint32_t a, uint32_t b) {
    int r;
    asm("vabsdiff2.s32.s32.s32.add %0, %1, %2, %3;"
        : "=r"(r) : "r"(a), "r"(b), "r"(acc));
    return r;
}
__device__ __forceinline__ void cp16(uint32_t dst_smem, const void* src) {
    asm volatile("cp.async.cg.shared.global [%0], [%1], 16;"
                 :: "r"(dst_smem), "l"(src));
}

__global__ void __launch_bounds__(NT, 2) l1attn_kernel(float* __restrict__ out)
{
    extern __shared__ __align__(16) __half smh[];
    __half* qh_sm = smh;                          // [512][40] halfs
    short*  qi_sm = (short*)(smh + Q_ELEM);       // [512][40] shorts
    __half* kh_sm0 = (__half*)(qi_sm + Q_ELEM);   // [64][40] x2 buffers
    __half* kh_sm1 = kh_sm0 + K_ELEM;
    short*  ki_sm0 = (short*)(kh_sm1 + K_ELEM);
    short*  ki_sm1 = ki_sm0 + K_ELEM;

    const int t   = threadIdx.x;
    const int j0  = blockIdx.x * JB;
    const int ig0 = blockIdx.y * NI;
    const int b   = blockIdx.z;

    const uint32_t qh_b = (uint32_t)__cvta_generic_to_shared(qh_sm);
    const uint32_t qi_b = (uint32_t)__cvta_generic_to_shared(qi_sm);
    const uint32_t kh_b[2] = { (uint32_t)__cvta_generic_to_shared(kh_sm0),
                               (uint32_t)__cvta_generic_to_shared(kh_sm1) };
    const uint32_t ki_b[2] = { (uint32_t)__cvta_generic_to_shared(ki_sm0),
                               (uint32_t)__cvta_generic_to_shared(ki_sm1) };

    // ---- Prologue: stage q (both types) + k tile 0 (both types) ----
    {
        const size_t qoff = ((size_t)b * S + j0) * (size_t)(H * DH);
        #pragma unroll
        for (int r = 0; r < (QR * 4) / NT; r++) {      // 8 iters
            int p = t + r * NT;  int row = p >> 2;  int sg = p & 3;
            cp16(qh_b + (row * RW + sg * 8) * 2, qh_g + qoff + row * DH + sg * 8);
        }
        #pragma unroll
        for (int r = 0; r < (QR * 4) / NT; r++) {      // 8 iters
            int p = t + r * NT;  int row = p >> 2;  int sg = p & 3;
            cp16(qi_b + (row * RW + sg * 8) * 2, qi_g + qoff + row * DH + sg * 8);
        }
        const size_t koff = ((size_t)b * S + ig0 * TI) * (size_t)(H * DH);
        #pragma unroll
        for (int r = 0; r < (KR * 4) / NT; r++) {      // 1 iter
            int p = t + r * NT;  int row = p >> 2;  int sg = p & 3;
            cp16(kh_b[0] + (row * RW + sg * 8) * 2, kh_g + koff + row * DH + sg * 8);
            cp16(ki_b[0] + (row * RW + sg * 8) * 2, ki_g + koff + row * DH + sg * 8);
        }
        asm volatile("cp.async.commit_group;" ::: "memory");
    }

    const int h  = t & 7;
    const int jl = (t >> 3) & 3;
    const int w  = t >> 5;
    const int slot  = w * 4 + jl;        // 0..31
    const int jbase = j0 + slot;         // u adds 32 j
    const int qrow0 = slot * 8 + h;      // u adds 32 j = 256 rows

    const __half2 hz = __float2half2_rn(0.0f);
    const float scale = -0.125f;  // -1/sqrt(64)

    #pragma unroll 1
    for (int n = 0; n < NI; n++) {
        // ---- Stage k(n+1) (both types), then wait for k(n) ----
        if (n + 1 < NI) {
            const size_t koff = ((size_t)b * S + (ig0 + n + 1) * TI) * (size_t)(H * DH);
            const int nb = (n + 1) & 1;
            #pragma unroll
            for (int r = 0; r < (KR * 4) / NT; r++) {
                int p = t + r * NT;  int row = p >> 2;  int sg = p & 3;
                cp16(kh_b[nb] + (row * RW + sg * 8) * 2, kh_g + koff + row * DH + sg * 8);
                cp16(ki_b[nb] + (row * RW + sg * 8) * 2, ki_g + koff + row * DH + sg * 8);
            }
            asm volatile("cp.async.commit_group;" ::: "memory");
            asm volatile("cp.async.wait_group 1;" ::: "memory");
        } else {
            asm volatile("cp.async.wait_group 0;" ::: "memory");
        }
        __syncthreads();

        const __half* kh_s = (n & 1) ? kh_sm1 : kh_sm0;
        const short*  ki_s = (n & 1) ? ki_sm1 : ki_sm0;

        __half2 h_acc[TI][NU];
        int     i_acc[TI][NU];
        #pragma unroll
        for (int i = 0; i < TI; i++)
            #pragma unroll
            for (int u = 0; u < NU; u++) { h_acc[i][u] = hz; i_acc[i][u] = 0; }

        #pragma unroll
        for (int s = 0; s < 4; s++) {            // 8 d per step, each path
            H8 qv[NU];  U4 qiv[NU];
            #pragma unroll
            for (int u = 0; u < NU; u++) {
                qv[u]  = *reinterpret_cast<const H8*>(
                    qh_sm + (qrow0 + u * 256) * RW + s * 8);
                qiv[u] = *reinterpret_cast<const U4*>(
                    qi_sm + (qrow0 + u * 256) * RW + s * 8);
            }
            const __half* kph = kh_s + h * RW + s * 8;
            const short*  kpi = ki_s + h * RW + s * 8;
            #pragma unroll
            for (int i = 0; i < TI; i++) {
                H8 kv  = *reinterpret_cast<const H8*>(kph + i * (8 * RW));
                U4 kiv = *reinterpret_cast<const U4*>(kpi + i * (8 * RW));
                #pragma unroll
                for (int u = 0; u < NU; u++) {
                    __half2 s0 = __hadd2(__habs2(__hsub2(kv.a, qv[u].a)),
                                         __habs2(__hsub2(kv.b, qv[u].b)));
                    __half2 s1 = __hadd2(__habs2(__hsub2(kv.c, qv[u].c)),
                                         __habs2(__hsub2(kv.d, qv[u].d)));
                    h_acc[i][u] = __hadd2(h_acc[i][u], __hadd2(s0, s1));
                    int a = i_acc[i][u];
                    a = sad2(a, kiv.x, qiv[u].x);
                    a = sad2(a, kiv.y, qiv[u].y);
                    a = sad2(a, kiv.z, qiv[u].z);
                    a = sad2(a, kiv.w, qiv[u].w);
                    i_acc[i][u] = a;
                }
            }
        }

        // ---- Stores for tile n ----
        const int i0 = (ig0 + n) * TI;
        #pragma unroll
        for (int i = 0; i < TI; i++) {
            const size_t ob = (((size_t)b * S + (i0 + i)) * S + jbase) * H + h;
            #pragma unroll
            for (int u = 0; u < NU; u++) {
                float2 f2 = __half22float2(h_acc[i][u]);
                float r = (f2.x + f2.y) + (float)i_acc[i][u] * SC_IR;
                out[ob + (size_t)u * (32 * H)] = r * scale;
            }
        }
        __syncthreads();   // reads of k buffers done before overwrite
    }
}

extern "C" void kernel_launch(void* const* d_in, const int* in_sizes, int n_in,
                              void* d_out, int out_size) {
    const float* q = (const float*)d_in[0];
    const float* k = (const float*)d_in[1];
    float* out     = (float*)d_out;

    cudaFuncSetAttribute(l1attn_kernel,
                         cudaFuncAttributeMaxDynamicSharedMemorySize, SMEM_BYTES);

    const int n4 = in_sizes[0] / 4;
    convert_kernel<<<(n4 + NT - 1) / NT, NT>>>(q, k, n4);

    const int B = in_sizes[0] / (S * H * D);  // = 8
    dim3 grid(S / JB, S / (TI * NI), B);
    l1attn_kernel<<<grid, NT, SMEM_BYTES>>>(out);
}

// round 17
// speedup vs baseline: 3.0035x; 3.0035x over previous
#include <cuda_runtime.h>
#include <cuda_fp16.h>
#include <cstdint>

// L1Attn: out[b,i,j,h] = -(1/8) * sum_d |q[b,j,h,d] - k[b,i,h,d]|
// B=8, S=1024, H=8, D=64. Output [B,S,S,H] (i = keys, j = queries).
//
// Two kernels: fp32->fp16 convert once; fp16x2 HSUB2/HADD2(|.|) mainloop
// (1 fma-pipe instr per term = the scalar-pipe floor). Persistent block over
// NI=4 i-tiles of TI=16 with q tile resident; k double-buffered cp.async.
// Full-tile fp16 accumulation, single fp32 merge in the epilogue.
// ROWH=72 (144 B rows) keeps every LDS.128 conflict-free.

namespace {
constexpr int S  = 1024;
constexpr int H  = 8;
constexpr int D  = 64;
constexpr int NT = 256;
constexpr int TI = 16;     // i per tile
constexpr int NI = 4;      // i-tiles per block (TI*NI = 64)
constexpr int JB = 64;     // j per block: 32 (w,jl) slots x 2 u
constexpr int NU = 2;      // j outputs per thread
constexpr int ROWH = 72;   // halfs per row: 64 d + 8 pad (conflict-free)
constexpr int QR  = JB * H;            // 512 q rows
constexpr int KR  = TI * H;            // 128 k rows
constexpr int QS_HALF = QR * ROWH;     // 36864 halfs (73728 B)
constexpr int KS_HALF = KR * ROWH;     // 9216  halfs (18432 B) per buffer
constexpr unsigned SMEM_BYTES = (QS_HALF + 2 * KS_HALF) * 2;  // 110592
constexpr int NELEM = 8 * S * H * D;
static_assert(S % JB == 0 && S % (TI * NI) == 0, "tiling must divide S");

struct __align__(8)  H4 { __half2 a, b; };
struct __align__(16) H8 { __half2 a, b, c, d; };
}  // namespace

__device__ __half qh_g[NELEM];
__device__ __half kh_g[NELEM];

__global__ void convert_kernel(const float* __restrict__ q,
                               const float* __restrict__ k, int n4) {
    int idx = blockIdx.x * blockDim.x + threadIdx.x;
    if (idx >= n4) return;
    float4 qv = reinterpret_cast<const float4*>(q)[idx];
    float4 kv = reinterpret_cast<const float4*>(k)[idx];
    H4 qh, kh;
    qh.a = __floats2half2_rn(qv.x, qv.y);
    qh.b = __floats2half2_rn(qv.z, qv.w);
    kh.a = __floats2half2_rn(kv.x, kv.y);
    kh.b = __floats2half2_rn(kv.z, kv.w);
    reinterpret_cast<H4*>(qh_g)[idx] = qh;
    reinterpret_cast<H4*>(kh_g)[idx] = kh;
}

__device__ __forceinline__ void cp16(uint32_t dst_smem, const __half* src) {
    asm volatile("cp.async.cg.shared.global [%0], [%1], 16;"
                 :: "r"(dst_smem), "l"(src));
}

__global__ void __launch_bounds__(NT, 2) l1attn_kernel(float* __restrict__ out)
{
    extern __shared__ __align__(16) __half smh[];
    __half* qsm   = smh;                      // q: [512 rows][72]
    __half* kbuf0 = smh + QS_HALF;            // k: [128 rows][72] x2
    __half* kbuf1 = kbuf0 + KS_HALF;

    const int t   = threadIdx.x;
    const int j0  = blockIdx.x * JB;
    const int ig0 = blockIdx.y * NI;          // first i-tile index
    const int b   = blockIdx.z;

    const uint32_t qsb  = (uint32_t)__cvta_generic_to_shared(qsm);
    const uint32_t ksb0 = (uint32_t)__cvta_generic_to_shared(kbuf0);
    const uint32_t ksb1 = (uint32_t)__cvta_generic_to_shared(kbuf1);

    // ---- Prologue: stage q tile (once) + k tile 0; one commit group ----
    {
        const __half* qt = qh_g + ((size_t)b * S + j0) * (size_t)(H * D);
        #pragma unroll
        for (int r = 0; r < (QR * 8) / NT; r++) {      // 16 iters
            int p   = t + r * NT;
            int row = p >> 3;
            int sg  = p & 7;
            cp16(qsb + (row * ROWH + sg * 8) * 2, qt + row * D + sg * 8);
        }
        const __half* kb = kh_g + ((size_t)b * S + ig0 * TI) * (size_t)(H * D);
        #pragma unroll
        for (int r = 0; r < (KR * 8) / NT; r++) {      // 4 iters
            int p   = t + r * NT;
            int row = p >> 3;
            int sg  = p & 7;
            cp16(ksb0 + (row * ROWH + sg * 8) * 2, kb + row * D + sg * 8);
        }
        asm volatile("cp.async.commit_group;" ::: "memory");
    }

    const int h  = t & 7;
    const int jl = (t >> 3) & 3;
    const int w  = t >> 5;
    const int slot  = w * 4 + jl;        // 0..31
    const int jbase = j0 + slot;         // u adds 32 j
    const int qrow0 = slot * 8 + h;      // u adds 32 j = 256 rows

    const __half2 hz = __float2half2_rn(0.0f);
    const float scale = -0.125f;  // -1/sqrt(64)

    #pragma unroll 1
    for (int n = 0; n < NI; n++) {
        // ---- Stage k(n+1) into the other buffer, then wait for k(n) ----
        if (n + 1 < NI) {
            const __half* kb = kh_g +
                ((size_t)b * S + (ig0 + n + 1) * TI) * (size_t)(H * D);
            uint32_t dstb = ((n + 1) & 1) ? ksb1 : ksb0;
            #pragma unroll
            for (int r = 0; r < (KR * 8) / NT; r++) {
                int p   = t + r * NT;
                int row = p >> 3;
                int sg  = p & 7;
                cp16(dstb + (row * ROWH + sg * 8) * 2, kb + row * D + sg * 8);
            }
            asm volatile("cp.async.commit_group;" ::: "memory");
            asm volatile("cp.async.wait_group 1;" ::: "memory");
        } else {
            asm volatile("cp.async.wait_group 0;" ::: "memory");
        }
        __syncthreads();   // k(n) (and q on n=0) visible to all

        const __half* ksm = (n & 1) ? kbuf1 : kbuf0;

        // ---- Full-tile fp16 accumulation: 8 steps of 8 d ----
        __half2 h_acc[TI][NU];
        #pragma unroll
        for (int i = 0; i < TI; i++)
            #pragma unroll
            for (int u = 0; u < NU; u++) h_acc[i][u] = hz;

        #pragma unroll
        for (int s = 0; s < 8; s++) {
            const int doff = s * 8;
            H8 qv[NU];
            #pragma unroll
            for (int u = 0; u < NU; u++)
                qv[u] = *reinterpret_cast<const H8*>(
                    qsm + (qrow0 + u * 256) * ROWH + doff);
            const __half* kp = ksm + h * ROWH + doff;
            #pragma unroll
            for (int i = 0; i < TI; i++) {
                H8 kv = *reinterpret_cast<const H8*>(kp + i * (8 * ROWH));
                #pragma unroll
                for (int u = 0; u < NU; u++) {
                    __half2 s0 = __hadd2(__habs2(__hsub2(kv.a, qv[u].a)),
                                         __habs2(__hsub2(kv.b, qv[u].b)));
                    __half2 s1 = __hadd2(__habs2(__hsub2(kv.c, qv[u].c)),
                                         __habs2(__hsub2(kv.d, qv[u].d)));
                    h_acc[i][u] = __hadd2(h_acc[i][u], __hadd2(s0, s1));
                }
            }
        }

        // ---- Epilogue for tile n: single fp32 merge + coalesced stores ----
        const int i0 = (ig0 + n) * TI;
        #pragma unroll
        for (int i = 0; i < TI; i++) {
            const size_t ob = (((size_t)b * S + (i0 + i)) * S + jbase) * H + h;
            #pragma unroll
            for (int u = 0; u < NU; u++) {
                float2 f2 = __half22float2(h_acc[i][u]);
                out[ob + (size_t)u * (32 * H)] = (f2.x + f2.y) * scale;
            }
        }
        __syncthreads();   // all reads of kbuf[n&1] done before overwrite
    }
}

extern "C" void kernel_launch(void* const* d_in, const int* in_sizes, int n_in,
                              void* d_out, int out_size) {
    const float* q = (const float*)d_in[0];
    const float* k = (const float*)d_in[1];
    float* out     = (float*)d_out;

    cudaFuncSetAttribute(l1attn_kernel,
                         cudaFuncAttributeMaxDynamicSharedMemorySize, SMEM_BYTES);

    const int n4 = in_sizes[0] / 4;
    convert_kernel<<<(n4 + NT - 1) / NT, NT>>>(q, k, n4);

    const int B = in_sizes[0] / (S * H * D);  // = 8
    dim3 grid(S / JB, S / (TI * NI), B);
    l1attn_kernel<<<grid, NT, SMEM_BYTES>>>(out);
}